// round 2
// baseline (speedup 1.0000x reference)
#include <cuda_runtime.h>
#include <cuda_bf16.h>

// Problem constants (fixed by the reference)
#define Cc    8
#define Ll    4096
#define Ff    32
#define Kk    10
#define PROC  20
#define STEP  5
#define NWIN  815          // == CHAN_OUT, no pad region
#define WPB   256          // windows per block
#define NTILE 4            // ceil(815/256)
#define FPAIR 16           // blockIdx.y range; thread handles f and f+16

// Shared x tile: covers WPB windows -> WPB*STEP + (PROC-STEP) = 1295 floats
#define SXN (WPB * STEP + PROC - STEP)

__global__ __launch_bounds__(WPB, 2)
void dtw_kernel(const float* __restrict__ x,
                const float* __restrict__ kernels,
                float* __restrict__ out)
{
    const int tile = blockIdx.x;          // window tile [0, NTILE)
    const int fp   = blockIdx.y;          // filter pair [0, 16): filters fp, fp+16
    const int bc   = blockIdx.z;          // b*C + c     [0, 64)
    const int tid  = threadIdx.x;

    __shared__ float sx[SXN];
    __shared__ float sk[2][Kk];

    // Kernel taps for the two filters of this block -> shared (broadcast LDS later)
    if (tid < 2 * Kk) {
        const int which = tid / Kk;
        const int i     = tid - which * Kk;
        sk[which][i] = kernels[(fp + which * FPAIR) * Kk + i];
    }

    // Cooperative, coalesced load of the x tile for this (b,c)
    const int    base = tile * WPB * STEP;
    const float* xc   = x + (size_t)bc * Ll;
    #pragma unroll
    for (int i = tid; i < SXN; i += WPB) {
        int g = base + i;
        sx[i] = (g < Ll) ? xc[g] : 0.0f;
    }
    __syncthreads();

    // Early-exit: threads without a real window do NO compute (tile 3: 209 idle)
    const int wg = tile * WPB + tid;
    if (wg >= NWIN) return;

    // Window: stride-5 shared reads, gcd(5,32)=1 -> conflict-free
    float w[PROC];
    #pragma unroll
    for (int j = 0; j < PROC; j++) w[j] = sx[tid * STEP + j];

    // Two independent DTW tables (filters fp and fp+16), interleaved for ILP=2.
    float a0[PROC], a1[PROC];

    // Row 0: cumulative sum of squared diffs
    {
        const float k0 = sk[0][0];
        const float k1 = sk[1][0];
        float d0 = k0 - w[0];
        float d1 = k1 - w[0];
        a0[0] = d0 * d0;
        a1[0] = d1 * d1;
        #pragma unroll
        for (int j = 1; j < PROC; j++) {
            d0 = k0 - w[j];
            d1 = k1 - w[j];
            a0[j] = fmaf(d0, d0, a0[j - 1]);
            a1[j] = fmaf(d1, d1, a1[j - 1]);
        }
    }

    // Rows 1..K-1. Keep the row loop rolled (code size / I$), inner fully unrolled.
    // Per cell-pair: 2 FADD + 2 FFMA (fma pipe) + 4 FMNMX (alu pipe) -> balanced.
    #pragma unroll 1
    for (int i = 1; i < Kk; i++) {
        const float k0 = sk[0][i];
        const float k1 = sk[1][i];
        float dg0 = a0[0];
        float dg1 = a1[0];
        float d0 = k0 - w[0];
        float d1 = k1 - w[0];
        a0[0] = fmaf(d0, d0, a0[0]);      // new[0] = d + prev[0]
        a1[0] = fmaf(d1, d1, a1[0]);
        #pragma unroll
        for (int j = 1; j < PROC; j++) {
            const float up0 = a0[j];
            const float up1 = a1[j];
            const float m0 = fminf(fminf(a0[j - 1], up0), dg0);
            const float m1 = fminf(fminf(a1[j - 1], up1), dg1);
            d0 = k0 - w[j];
            d1 = k1 - w[j];
            a0[j] = fmaf(d0, d0, m0);
            a1[j] = fmaf(d1, d1, m1);
            dg0 = up0;
            dg1 = up1;
        }
    }

    // out[b, c*F + f, w]; coalesced in w for each filter
    const size_t o0 = ((size_t)bc * Ff + fp) * NWIN + wg;
    out[o0]                        = a0[PROC - 1];
    out[o0 + (size_t)FPAIR * NWIN] = a1[PROC - 1];
}

extern "C" void kernel_launch(void* const* d_in, const int* in_sizes, int n_in,
                              void* d_out, int out_size)
{
    const float* x       = (const float*)d_in[0];   // (8, 8, 4096) f32
    const float* kernels = (const float*)d_in[1];   // (32, 10) f32
    float*       out     = (float*)d_out;           // (8, 256, 815) f32

    (void)in_sizes; (void)n_in; (void)out_size;

    dim3 grid(NTILE, FPAIR, 8 * Cc);   // (4, 16, 64)
    dtw_kernel<<<grid, WPB>>>(x, kernels, out);
}

// round 3
// speedup vs baseline: 1.0072x; 1.0072x over previous
#include <cuda_runtime.h>
#include <cuda_bf16.h>

// Problem constants (fixed by the reference)
#define Cc    8
#define Ll    4096
#define Ff    32
#define Kk    10
#define PROC  20
#define STEP  5
#define NWIN  815          // == CHAN_OUT, no pad region
#define WPB   256          // windows per block
#define NTILE 4            // ceil(815/256)

// Shared x tile: covers WPB windows -> WPB*STEP + (PROC-STEP) = 1295 floats
#define SXN (WPB * STEP + PROC - STEP)

__global__ __launch_bounds__(WPB, 4)
void dtw_kernel(const float* __restrict__ x,
                const float* __restrict__ kernels,
                float* __restrict__ out)
{
    const int tile = blockIdx.x;          // window tile [0, NTILE)
    const int f    = blockIdx.y;          // filter     [0, Ff)
    const int bc   = blockIdx.z;          // b*C + c    [0, 64)
    const int tid  = threadIdx.x;

    __shared__ float sx[SXN];
    __shared__ float sk[Kk];

    // Kernel taps for this filter -> shared (broadcast LDS per row later)
    if (tid < Kk) sk[tid] = kernels[f * Kk + tid];

    // Cooperative, coalesced load of the x tile for this (b,c)
    const int    base = tile * WPB * STEP;
    const float* xc   = x + (size_t)bc * Ll;
    #pragma unroll
    for (int i = tid; i < SXN; i += WPB) {
        int g = base + i;
        sx[i] = (g < Ll) ? xc[g] : 0.0f;
    }
    __syncthreads();

    // Early-exit: threads without a real window do no compute (no syncs below)
    const int wg = tile * WPB + tid;
    if (wg >= NWIN) return;

    // Window: stride-5 shared reads, gcd(5,32)=1 -> conflict-free
    float w[PROC];
    #pragma unroll
    for (int j = 0; j < PROC; j++) w[j] = sx[tid * STEP + j];

    // DTW table, row-sweep with register-resident row of length PROC.
    float acc[PROC];

    // Row 0: cumulative sum of squared diffs
    {
        const float k0 = sk[0];
        float d = k0 - w[0];
        acc[0] = d * d;
        #pragma unroll
        for (int j = 1; j < PROC; j++) {
            d = k0 - w[j];
            acc[j] = fmaf(d, d, acc[j - 1]);
        }
    }

    // Rows 1..K-1. Outer loop rolled (code size / I$), inner fully unrolled.
    // Reassociated min: pmin = min(up, diag) is OFF the left-dependency chain,
    // so the serial path per cell is FMNMX(left,pmin) -> FFMA  (~10 cyc).
    #pragma unroll 1
    for (int i = 1; i < Kk; i++) {
        const float kv = sk[i];
        float diag = acc[0];              // old prev[0]
        float d = kv - w[0];
        acc[0] = fmaf(d, d, acc[0]);      // new[0] = d + prev[0]
        #pragma unroll
        for (int j = 1; j < PROC; j++) {
            const float up   = acc[j];            // prev[j]
            const float pmin = fminf(up, diag);   // independent of the chain
            const float m    = fminf(acc[j - 1], pmin);
            d = kv - w[j];
            acc[j] = fmaf(d, d, m);
            diag = up;                            // prev[j] -> diag for j+1
        }
    }

    // out[b, c*F + f, w]: coalesced in w
    out[((size_t)bc * Ff + f) * NWIN + wg] = acc[PROC - 1];
}

extern "C" void kernel_launch(void* const* d_in, const int* in_sizes, int n_in,
                              void* d_out, int out_size)
{
    const float* x       = (const float*)d_in[0];   // (8, 8, 4096) f32
    const float* kernels = (const float*)d_in[1];   // (32, 10) f32
    float*       out     = (float*)d_out;           // (8, 256, 815) f32

    (void)in_sizes; (void)n_in; (void)out_size;

    dim3 grid(NTILE, Ff, 8 * Cc);   // (4, 32, 64)
    dtw_kernel<<<grid, WPB>>>(x, kernels, out);
}

// round 4
// speedup vs baseline: 1.2087x; 1.2000x over previous
#include <cuda_runtime.h>
#include <cuda_bf16.h>

// Problem constants (fixed by the reference)
#define Cc    8
#define Ll    4096
#define Ff    32
#define Kk    10
#define PROC  20
#define STEP  5
#define NWIN  815          // == CHAN_OUT, no pad region
#define WPB   256          // windows per block
#define NTILE 4            // ceil(815/256)

// Shared x tile: covers WPB windows -> WPB*STEP + (PROC-STEP) = 1295 floats
#define SXN (WPB * STEP + PROC - STEP)

__global__ __launch_bounds__(WPB, 2)
void dtw_kernel(const float* __restrict__ x,
                const float* __restrict__ kernels,
                float* __restrict__ out)
{
    const int tile = blockIdx.x;          // window tile [0, NTILE)
    const int f    = blockIdx.y;          // filter     [0, Ff)
    const int bc   = blockIdx.z;          // b*C + c    [0, 64)
    const int tid  = threadIdx.x;

    __shared__ float sx[SXN];

    // Cooperative, coalesced load of the x tile for this (b,c)
    const int    base = tile * WPB * STEP;
    const float* xc   = x + (size_t)bc * Ll;
    #pragma unroll
    for (int i = tid; i < SXN; i += WPB) {
        int g = base + i;
        sx[i] = (g < Ll) ? xc[g] : 0.0f;
    }
    __syncthreads();

    // Early-exit: lanes without a real window skip ALL compute.
    // (No syncs below this point, so divergence-safe.)
    const int wg = tile * WPB + tid;
    if (wg >= NWIN) return;

    // Kernel taps: warp-uniform addresses -> broadcast loads, L1-resident
    float ker[Kk];
    #pragma unroll
    for (int i = 0; i < Kk; i++) ker[i] = __ldg(&kernels[f * Kk + i]);

    // Window: stride-5 shared reads, gcd(5,32)=1 -> conflict-free
    float w[PROC];
    #pragma unroll
    for (int j = 0; j < PROC; j++) w[j] = sx[tid * STEP + j];

    // DTW table, row-sweep with register-resident row of length PROC.
    // Everything fully unrolled: register renaming kills all rotation MOVs.
    float acc[PROC];

    // Row 0: cumulative sum of squared diffs
    {
        const float k0 = ker[0];
        float d = k0 - w[0];
        acc[0] = d * d;
        #pragma unroll
        for (int j = 1; j < PROC; j++) {
            d = k0 - w[j];
            acc[j] = fmaf(d, d, acc[j - 1]);
        }
    }

    // Rows 1..K-1, fully unrolled. Reassociated min: pmin = min(up, diag)
    // is off the left-dependency chain -> serial path = FMNMX + FFMA (~10 cyc).
    #pragma unroll
    for (int i = 1; i < Kk; i++) {
        const float kv = ker[i];
        float diag = acc[0];              // old prev[0]
        float d = kv - w[0];
        acc[0] = fmaf(d, d, acc[0]);      // new[0] = d + prev[0]
        #pragma unroll
        for (int j = 1; j < PROC; j++) {
            const float up   = acc[j];            // prev[j]
            const float pmin = fminf(up, diag);   // independent of the chain
            const float m    = fminf(acc[j - 1], pmin);
            d = kv - w[j];
            acc[j] = fmaf(d, d, m);
            diag = up;                            // renamed away by unroll
        }
    }

    // out[b, c*F + f, w]: coalesced in w
    out[((size_t)bc * Ff + f) * NWIN + wg] = acc[PROC - 1];
}

extern "C" void kernel_launch(void* const* d_in, const int* in_sizes, int n_in,
                              void* d_out, int out_size)
{
    const float* x       = (const float*)d_in[0];   // (8, 8, 4096) f32
    const float* kernels = (const float*)d_in[1];   // (32, 10) f32
    float*       out     = (float*)d_out;           // (8, 256, 815) f32

    (void)in_sizes; (void)n_in; (void)out_size;

    dim3 grid(NTILE, Ff, 8 * Cc);   // (4, 32, 64)
    dtw_kernel<<<grid, WPB>>>(x, kernels, out);
}

// round 5
// speedup vs baseline: 1.2144x; 1.0047x over previous
#include <cuda_runtime.h>
#include <cuda_bf16.h>

// Problem constants (fixed by the reference)
#define Cc    8
#define Ll    4096
#define Ff    32
#define Kk    10
#define PROC  20
#define STEP  5
#define NWIN  815          // == CHAN_OUT, no pad region
#define WPB   256          // windows per block
#define NTILE 4            // ceil(815/256)

// Shared x tile: covers WPB windows -> WPB*STEP + (PROC-STEP) = 1295 floats
#define SXN (WPB * STEP + PROC - STEP)

__global__ __launch_bounds__(WPB, 3)
void dtw_kernel(const float* __restrict__ x,
                const float* __restrict__ kernels,
                float* __restrict__ out)
{
    const int tile = blockIdx.x;          // window tile [0, NTILE)
    const int f    = blockIdx.y;          // filter     [0, Ff)
    const int bc   = blockIdx.z;          // b*C + c    [0, 64)
    const int tid  = threadIdx.x;

    __shared__ float sx[SXN];

    // Cooperative, coalesced load of the x tile for this (b,c)
    const int    base = tile * WPB * STEP;
    const float* xc   = x + (size_t)bc * Ll;
    #pragma unroll
    for (int i = tid; i < SXN; i += WPB) {
        int g = base + i;
        sx[i] = (g < Ll) ? xc[g] : 0.0f;
    }
    __syncthreads();

    // Early-exit: lanes without a real window skip ALL compute.
    // (No syncs below this point, so divergence-safe.)
    const int wg = tile * WPB + tid;
    if (wg >= NWIN) return;

    // Kernel taps: warp-uniform addresses -> broadcast loads, L1-resident
    float ker[Kk];
    #pragma unroll
    for (int i = 0; i < Kk; i++) ker[i] = __ldg(&kernels[f * Kk + i]);

    // Window: stride-5 shared reads, gcd(5,32)=1 -> conflict-free
    float w[PROC];
    #pragma unroll
    for (int j = 0; j < PROC; j++) w[j] = sx[tid * STEP + j];

    // DTW table, row-sweep with register-resident row of length PROC.
    // Everything fully unrolled: register renaming kills all rotation MOVs.
    float acc[PROC];

    // Row 0: cumulative sum of squared diffs
    {
        const float k0 = ker[0];
        float d = k0 - w[0];
        acc[0] = d * d;
        #pragma unroll
        for (int j = 1; j < PROC; j++) {
            d = k0 - w[j];
            acc[j] = fmaf(d, d, acc[j - 1]);
        }
    }

    // Rows 1..K-1, fully unrolled. Reassociated min: pmin = min(up, diag)
    // is off the left-dependency chain -> serial path = FMNMX + FFMA (~10 cyc).
    #pragma unroll
    for (int i = 1; i < Kk; i++) {
        const float kv = ker[i];
        float diag = acc[0];              // old prev[0]
        float d = kv - w[0];
        acc[0] = fmaf(d, d, acc[0]);      // new[0] = d + prev[0]
        #pragma unroll
        for (int j = 1; j < PROC; j++) {
            const float up   = acc[j];            // prev[j]
            const float pmin = fminf(up, diag);   // independent of the chain
            const float m    = fminf(acc[j - 1], pmin);
            d = kv - w[j];
            acc[j] = fmaf(d, d, m);
            diag = up;                            // renamed away by unroll
        }
    }

    // out[b, c*F + f, w]: coalesced in w
    out[((size_t)bc * Ff + f) * NWIN + wg] = acc[PROC - 1];
}

extern "C" void kernel_launch(void* const* d_in, const int* in_sizes, int n_in,
                              void* d_out, int out_size)
{
    const float* x       = (const float*)d_in[0];   // (8, 8, 4096) f32
    const float* kernels = (const float*)d_in[1];   // (32, 10) f32
    float*       out     = (float*)d_out;           // (8, 256, 815) f32

    (void)in_sizes; (void)n_in; (void)out_size;

    dim3 grid(NTILE, Ff, 8 * Cc);   // (4, 32, 64)
    dtw_kernel<<<grid, WPB>>>(x, kernels, out);
}